// round 6
// baseline (speedup 1.0000x reference)
#include <cuda_runtime.h>
#include <math.h>
#include <cfloat>
#include <stdint.h>

// ---------------- problem dims (fixed) ----------------
#define NTOT  65536      // nodes per side (B*N)
#define NEDGE 524288     // edges per side
#define NB    128        // graphs
#define NPG   512        // nodes per graph
#define D_F1  128
#define D_F2  96
#define D_F3  64
#define D_BINS 16

// ---------------- device scratch ----------------
__device__ float g_buf0[NTOT * D_F1];
__device__ float g_buf1[NTOT * D_F1];
__device__ float g_feat[2][NTOT * D_F3];
__device__ float g_dinv[2][NTOT];
__device__ int   g_degi[2][NTOT];
__device__ int   g_row[2][NTOT + 1];
__device__ int   g_cursor[2][NTOT];
__device__ int   g_bsum[2][256];
__device__ int   g_boff[2][256];
__device__ int   g_esrc[2][NEDGE];
__device__ float g_enorm[2][NEDGE];
__device__ float g_sim[(size_t)NB * NPG * NPG];
__device__ int   g_hist[NB * D_BINS];
__device__ float g_smin[NB];
__device__ float g_smax[NB];
__device__ float g_pool[2][NB * D_F3];

__device__ __forceinline__ float sigmoidf_(float x) { return 1.0f / (1.0f + expf(-x)); }

__device__ __forceinline__ void atomicMinFloat(float* addr, float val) {
    int old = __float_as_int(*addr);
    while (__int_as_float(old) > val) {
        int assumed = old;
        old = atomicCAS((int*)addr, assumed, __float_as_int(val));
        if (old == assumed) break;
    }
}
__device__ __forceinline__ void atomicMaxFloat(float* addr, float val) {
    int old = __float_as_int(*addr);
    while (__int_as_float(old) < val) {
        int assumed = old;
        old = atomicCAS((int*)addr, assumed, __float_as_int(val));
        if (old == assumed) break;
    }
}

// ---------------- tf32 helpers (3xTF32 fp32-emulation split) ----------------
__device__ __forceinline__ uint32_t f2tf32(float x) {
    uint32_t r;
    asm("cvt.rna.tf32.f32 %0, %1;" : "=r"(r) : "f"(x));
    return r;
}
__device__ __forceinline__ void split_tf32(float x, uint32_t& hi, uint32_t& lo) {
    hi = f2tf32(x);
    lo = f2tf32(x - __uint_as_float(hi));
}
__device__ __forceinline__ void mma_tf32(float* d, const uint32_t* a, const uint32_t* b) {
    asm volatile(
        "mma.sync.aligned.m16n8k8.row.col.f32.tf32.tf32.f32 "
        "{%0,%1,%2,%3}, {%4,%5,%6,%7}, {%8,%9}, {%0,%1,%2,%3};\n"
        : "+f"(d[0]), "+f"(d[1]), "+f"(d[2]), "+f"(d[3])
        : "r"(a[0]), "r"(a[1]), "r"(a[2]), "r"(a[3]), "r"(b[0]), "r"(b[1]));
}

// block-wide exclusive scan of 256 ints (one value per thread)
__device__ __forceinline__ int block_exscan_256(int v, int* sm8) {
    int lane = threadIdx.x & 31, w = threadIdx.x >> 5;
    int x = v;
#pragma unroll
    for (int o = 1; o < 32; o <<= 1) {
        int y = __shfl_up_sync(0xffffffffu, x, o);
        if (lane >= o) x += y;
    }
    if (lane == 31) sm8[w] = x;
    __syncthreads();
    if (threadIdx.x < 8) {
        int s = sm8[threadIdx.x];
#pragma unroll
        for (int o = 1; o < 8; o <<= 1) {
            int y = __shfl_up_sync(0xffu, s, o);
            if ((int)threadIdx.x >= o) s += y;
        }
        sm8[threadIdx.x] = s;
    }
    __syncthreads();
    int woff = w ? sm8[w - 1] : 0;
    return woff + x - v;
}

// ---------------- init ----------------
__global__ void init_k() {
    int i = blockIdx.x * blockDim.x + threadIdx.x;
    if (i < NTOT) { g_degi[0][i] = 0; g_degi[1][i] = 0; }
    if (i < NB * D_BINS) g_hist[i] = 0;
    if (i < NB) { g_smin[i] = FLT_MAX; g_smax[i] = -FLT_MAX; }
}

// ---------------- degree / dinv (both sides via grid.y) ----------------
__global__ void deg_k(const int* __restrict__ dst0, const int* __restrict__ dst1) {
    int side = blockIdx.y;
    const int* dst = side ? dst1 : dst0;
    int e = blockIdx.x * blockDim.x + threadIdx.x;
    if (e < NEDGE) atomicAdd(&g_degi[side][dst[e]], 1);
}
__global__ void dinv_k() {
    int side = blockIdx.y;
    int i = blockIdx.x * blockDim.x + threadIdx.x;
    if (i < NTOT) g_dinv[side][i] = rsqrtf((float)g_degi[side][i] + 1.0f);
}

// ---------------- 3-phase parallel scan ----------------
__global__ void scanA_k() {
    int side = blockIdx.y;
    int i = blockIdx.x * 256 + threadIdx.x;
    int v = g_degi[side][i];
#pragma unroll
    for (int o = 16; o; o >>= 1) v += __shfl_xor_sync(0xffffffffu, v, o);
    __shared__ int sm[8];
    if ((threadIdx.x & 31) == 0) sm[threadIdx.x >> 5] = v;
    __syncthreads();
    if (threadIdx.x == 0) {
        int s = 0;
#pragma unroll
        for (int j = 0; j < 8; j++) s += sm[j];
        g_bsum[side][blockIdx.x] = s;
    }
}
__global__ void scanB_k() {
    int side = blockIdx.x;
    __shared__ int sm[8];
    int v = g_bsum[side][threadIdx.x];
    int ex = block_exscan_256(v, sm);
    g_boff[side][threadIdx.x] = ex + v;
}
__global__ void scanC_k() {
    int side = blockIdx.y;
    int i = blockIdx.x * 256 + threadIdx.x;
    int d = g_degi[side][i];
    __shared__ int sm[8];
    int ex = block_exscan_256(d, sm);
    int off = (blockIdx.x ? g_boff[side][blockIdx.x - 1] : 0) + ex;
    g_row[side][i] = off;
    g_cursor[side][i] = off;
    if (i == NTOT - 1) g_row[side][NTOT] = NEDGE;
}

// ---------------- scatter edges into CSR order ----------------
__global__ void scatter_k(const int* __restrict__ ei0, const int* __restrict__ ei1) {
    int side = blockIdx.y;
    const int* ei = side ? ei1 : ei0;
    const int* src = ei;
    const int* dst = ei + NEDGE;
    int e = blockIdx.x * blockDim.x + threadIdx.x;
    if (e >= NEDGE) return;
    int s = src[e], d = dst[e];
    int pos = atomicAdd(&g_cursor[side][d], 1);
    g_esrc[side][pos] = s;
    g_enorm[side][pos] = g_dinv[side][s] * g_dinv[side][d];
}

// ---------------- SMEM-staged aggregation (one block per graph) -----------
// Stages the graph's 512xOUT feature block in dynamic SMEM; all neighbor
// gathers hit SMEM. Edges never cross graph boundaries.
template <int OUT, bool BIAS, bool RELU>
__global__ void agg_smem_k(const float* __restrict__ xw, const float* __restrict__ bias,
                           float* __restrict__ out, int side) {
    extern __shared__ float sf[];                 // NPG * OUT floats
    constexpr int C4 = OUT / 4;
    int g = blockIdx.x;
    int base = g * NPG;
    const float4* src4 = (const float4*)(xw + (size_t)base * OUT);
    float4* sf4 = (float4*)sf;
    for (int i = threadIdx.x; i < NPG * C4; i += blockDim.x) sf4[i] = src4[i];
    __syncthreads();

    float4* out4 = (float4*)(out + (size_t)base * OUT);
    for (int w = threadIdx.x; w < NPG * C4; w += blockDim.x) {
        int node = w / C4, chunk = w % C4;
        int gnode = base + node;
        float dv = g_dinv[side][gnode];
        float dv2 = dv * dv;
        float4 v = sf4[node * C4 + chunk];
        float4 acc = make_float4(v.x * dv2, v.y * dv2, v.z * dv2, v.w * dv2);
        int beg = g_row[side][gnode], end = g_row[side][gnode + 1];
        for (int e = beg; e < end; e++) {
            int s = g_esrc[side][e] - base;       // local index
            float nm = g_enorm[side][e];
            float4 u = sf4[s * C4 + chunk];
            acc.x += u.x * nm; acc.y += u.y * nm; acc.z += u.z * nm; acc.w += u.w * nm;
        }
        if (BIAS) {
            acc.x += bias[chunk * 4 + 0];
            acc.y += bias[chunk * 4 + 1];
            acc.z += bias[chunk * 4 + 2];
            acc.w += bias[chunk * 4 + 3];
        }
        if (RELU) {
            acc.x = fmaxf(acc.x, 0.f); acc.y = fmaxf(acc.y, 0.f);
            acc.z = fmaxf(acc.z, 0.f); acc.w = fmaxf(acc.w, 0.f);
        }
        out4[w] = acc;
    }
}

// ---------------- 3xTF32 tensor-core GEMM: out = x @ W (+b, relu) ----------
template <int KIN, int NOUT, bool BIAS, bool RELU>
__global__ void gemm_mma_k(const float* __restrict__ x, const float* __restrict__ W,
                           const float* __restrict__ bias, float* __restrict__ out) {
    constexpr int KC = 16;
    constexpr int NT = NOUT / 8;
    constexpr int XS = KC + 4;
    constexpr int WS = NOUT + 8;
    __shared__ uint32_t Xh[128 * XS];
    __shared__ uint32_t Xl[128 * XS];
    __shared__ uint32_t Wh[KC * WS];
    __shared__ uint32_t Wl[KC * WS];
    int tid = threadIdx.x;
    int warp = tid >> 5, lane = tid & 31;
    size_t m0 = (size_t)blockIdx.x * 128;
    float acc[NT][4];
#pragma unroll
    for (int i = 0; i < NT; i++)
#pragma unroll
        for (int j = 0; j < 4; j++) acc[i][j] = 0.0f;

    for (int k0 = 0; k0 < KIN; k0 += KC) {
        for (int i = tid; i < 128 * (KC / 4); i += 256) {
            int r = i / (KC / 4), q = i % (KC / 4);
            float4 v = *(const float4*)&x[(m0 + r) * KIN + k0 + q * 4];
            uint32_t* ph = &Xh[r * XS + q * 4];
            uint32_t* pl = &Xl[r * XS + q * 4];
            split_tf32(v.x, ph[0], pl[0]); split_tf32(v.y, ph[1], pl[1]);
            split_tf32(v.z, ph[2], pl[2]); split_tf32(v.w, ph[3], pl[3]);
        }
        for (int i = tid; i < KC * NOUT / 4; i += 256) {
            int k = i / (NOUT / 4), q = i % (NOUT / 4);
            float4 v = *(const float4*)&W[(size_t)(k0 + k) * NOUT + q * 4];
            uint32_t* ph = &Wh[k * WS + q * 4];
            uint32_t* pl = &Wl[k * WS + q * 4];
            split_tf32(v.x, ph[0], pl[0]); split_tf32(v.y, ph[1], pl[1]);
            split_tf32(v.z, ph[2], pl[2]); split_tf32(v.w, ph[3], pl[3]);
        }
        __syncthreads();
#pragma unroll
        for (int ks = 0; ks < KC / 8; ks++) {
            uint32_t ah[4], al[4];
            int arow = warp * 16 + (lane >> 2);
            int acol = ks * 8 + (lane & 3);
            ah[0] = Xh[arow * XS + acol];       al[0] = Xl[arow * XS + acol];
            ah[1] = Xh[(arow + 8) * XS + acol]; al[1] = Xl[(arow + 8) * XS + acol];
            ah[2] = Xh[arow * XS + acol + 4];   al[2] = Xl[arow * XS + acol + 4];
            ah[3] = Xh[(arow + 8) * XS + acol + 4]; al[3] = Xl[(arow + 8) * XS + acol + 4];
            int bk = ks * 8 + (lane & 3);
            int bn0 = lane >> 2;
#pragma unroll
            for (int nt = 0; nt < NT; nt++) {
                uint32_t bh[2], bl[2];
                bh[0] = Wh[bk * WS + nt * 8 + bn0];
                bh[1] = Wh[(bk + 4) * WS + nt * 8 + bn0];
                bl[0] = Wl[bk * WS + nt * 8 + bn0];
                bl[1] = Wl[(bk + 4) * WS + nt * 8 + bn0];
                mma_tf32(acc[nt], ah, bh);
                mma_tf32(acc[nt], ah, bl);
                mma_tf32(acc[nt], al, bh);
            }
        }
        __syncthreads();
    }
    size_t row = m0 + warp * 16 + (lane >> 2);
    int col0 = (lane & 3) * 2;
#pragma unroll
    for (int nt = 0; nt < NT; nt++) {
        int c = nt * 8 + col0;
        float b0 = BIAS ? bias[c] : 0.0f, b1 = BIAS ? bias[c + 1] : 0.0f;
        float v0 = acc[nt][0] + b0, v1 = acc[nt][1] + b1;
        float v2 = acc[nt][2] + b0, v3 = acc[nt][3] + b1;
        if (RELU) {
            v0 = fmaxf(v0, 0.f); v1 = fmaxf(v1, 0.f);
            v2 = fmaxf(v2, 0.f); v3 = fmaxf(v3, 0.f);
        }
        *(float2*)&out[row * NOUT + c] = make_float2(v0, v1);
        *(float2*)&out[(row + 8) * NOUT + c] = make_float2(v2, v3);
    }
}

// ---------------- attention pooling (one block per graph) ----------------
__global__ void pool_k(int side, const float* __restrict__ Watt) {
    int b = blockIdx.x;
    const float* fb = &g_feat[side][(size_t)b * NPG * D_F3];
    int t = threadIdx.x;  // 256
    __shared__ float p4[4][64];
    __shared__ float meanc[64];
    __shared__ float ctx[64];
    __shared__ float wsum[8][64];
    int d = t & 63, g = t >> 6;
    float loc = 0.0f;
    for (int r = g; r < NPG; r += 4) loc += fb[r * 64 + d];
    p4[g][d] = loc;
    __syncthreads();
    if (t < 64) meanc[t] = (p4[0][t] + p4[1][t] + p4[2][t] + p4[3][t]) * (1.0f / NPG);
    __syncthreads();
    if (t < 64) {
        float c = 0.0f;
        for (int i = 0; i < 64; i++) c += meanc[i] * Watt[i * 64 + t];
        ctx[t] = tanhf(c);
    }
    __syncthreads();
    int w = t >> 5, l = t & 31;
    float a0 = 0.0f, a1 = 0.0f;
    float c0 = ctx[l], c1 = ctx[l + 32];
    for (int r = w * 64; r < w * 64 + 64; r++) {
        float v0 = fb[r * 64 + l], v1 = fb[r * 64 + 32 + l];
        float dp = v0 * c0 + v1 * c1;
#pragma unroll
        for (int o = 16; o; o >>= 1) dp += __shfl_xor_sync(0xffffffffu, dp, o);
        float coef = sigmoidf_(dp);
        a0 += v0 * coef;
        a1 += v1 * coef;
    }
    wsum[w][l] = a0;
    wsum[w][l + 32] = a1;
    __syncthreads();
    if (t < 64) {
        float s = 0.0f;
        for (int w2 = 0; w2 < 8; w2++) s += wsum[w2][t];
        g_pool[side][b * 64 + t] = s;
    }
}

// ---------------- similarity via 3xTF32 mma, 128x128 tile ----------------
__global__ void sim_mma_k() {
    constexpr int KC = 16;
    constexpr int XS = KC + 4;
    int b = blockIdx.z;
    int i0 = blockIdx.y * 128, j0 = blockIdx.x * 128;
    __shared__ uint32_t Ah_s[128 * XS];
    __shared__ uint32_t Al_s[128 * XS];
    __shared__ uint32_t Bh_s[128 * XS];
    __shared__ uint32_t Bl_s[128 * XS];
    const float* f1 = &g_feat[0][(size_t)(b * NPG + i0) * 64];
    const float* f2 = &g_feat[1][(size_t)(b * NPG + j0) * 64];
    int tid = threadIdx.x;
    int warp = tid >> 5, lane = tid & 31;
    int wm = warp >> 2, wn = warp & 3;
    float acc[4][4][4];
#pragma unroll
    for (int mt = 0; mt < 4; mt++)
#pragma unroll
        for (int nt = 0; nt < 4; nt++)
#pragma unroll
            for (int j = 0; j < 4; j++) acc[mt][nt][j] = 0.0f;

    for (int k0 = 0; k0 < 64; k0 += KC) {
        for (int i = tid; i < 128 * (KC / 4); i += 256) {
            int r = i / (KC / 4), q = i % (KC / 4);
            float4 va = *(const float4*)&f1[r * 64 + k0 + q * 4];
            float4 vb = *(const float4*)&f2[r * 64 + k0 + q * 4];
            uint32_t* pah = &Ah_s[r * XS + q * 4];
            uint32_t* pal = &Al_s[r * XS + q * 4];
            uint32_t* pbh = &Bh_s[r * XS + q * 4];
            uint32_t* pbl = &Bl_s[r * XS + q * 4];
            split_tf32(va.x, pah[0], pal[0]); split_tf32(va.y, pah[1], pal[1]);
            split_tf32(va.z, pah[2], pal[2]); split_tf32(va.w, pah[3], pal[3]);
            split_tf32(vb.x, pbh[0], pbl[0]); split_tf32(vb.y, pbh[1], pbl[1]);
            split_tf32(vb.z, pbh[2], pbl[2]); split_tf32(vb.w, pbh[3], pbl[3]);
        }
        __syncthreads();
#pragma unroll
        for (int ks = 0; ks < KC / 8; ks++) {
            int acol = ks * 8 + (lane & 3);
            uint32_t ah[4][4], al[4][4], bh[4][2], bl[4][2];
#pragma unroll
            for (int mt = 0; mt < 4; mt++) {
                int arow = wm * 64 + mt * 16 + (lane >> 2);
                ah[mt][0] = Ah_s[arow * XS + acol];
                ah[mt][1] = Ah_s[(arow + 8) * XS + acol];
                ah[mt][2] = Ah_s[arow * XS + acol + 4];
                ah[mt][3] = Ah_s[(arow + 8) * XS + acol + 4];
                al[mt][0] = Al_s[arow * XS + acol];
                al[mt][1] = Al_s[(arow + 8) * XS + acol];
                al[mt][2] = Al_s[arow * XS + acol + 4];
                al[mt][3] = Al_s[(arow + 8) * XS + acol + 4];
            }
#pragma unroll
            for (int nt = 0; nt < 4; nt++) {
                int bnode = wn * 32 + nt * 8 + (lane >> 2);
                bh[nt][0] = Bh_s[bnode * XS + acol];
                bh[nt][1] = Bh_s[bnode * XS + acol + 4];
                bl[nt][0] = Bl_s[bnode * XS + acol];
                bl[nt][1] = Bl_s[bnode * XS + acol + 4];
            }
#pragma unroll
            for (int mt = 0; mt < 4; mt++)
#pragma unroll
                for (int nt = 0; nt < 4; nt++) {
                    mma_tf32(acc[mt][nt], ah[mt], bh[nt]);
                    mma_tf32(acc[mt][nt], ah[mt], bl[nt]);
                    mma_tf32(acc[mt][nt], al[mt], bh[nt]);
                }
        }
        __syncthreads();
    }
    float lmin = FLT_MAX, lmax = -FLT_MAX;
    float* sp = &g_sim[(size_t)b * NPG * NPG];
    int col0 = (lane & 3) * 2;
#pragma unroll
    for (int mt = 0; mt < 4; mt++) {
        size_t r0 = (size_t)(i0 + wm * 64 + mt * 16 + (lane >> 2));
#pragma unroll
        for (int nt = 0; nt < 4; nt++) {
            int c = j0 + wn * 32 + nt * 8 + col0;
            float v0 = acc[mt][nt][0], v1 = acc[mt][nt][1];
            float v2 = acc[mt][nt][2], v3 = acc[mt][nt][3];
            lmin = fminf(lmin, fminf(fminf(v0, v1), fminf(v2, v3)));
            lmax = fmaxf(lmax, fmaxf(fmaxf(v0, v1), fmaxf(v2, v3)));
            *(float2*)&sp[r0 * NPG + c] = make_float2(v0, v1);
            *(float2*)&sp[(r0 + 8) * NPG + c] = make_float2(v2, v3);
        }
    }
    __shared__ float rmin[256], rmax[256];
    rmin[tid] = lmin;
    rmax[tid] = lmax;
    __syncthreads();
    for (int s = 128; s > 0; s >>= 1) {
        if (tid < s) {
            rmin[tid] = fminf(rmin[tid], rmin[tid + s]);
            rmax[tid] = fmaxf(rmax[tid], rmax[tid + s]);
        }
        __syncthreads();
    }
    if (tid == 0) {
        atomicMinFloat(&g_smin[b], rmin[0]);
        atomicMaxFloat(&g_smax[b], rmax[0]);
    }
}

// ---------------- histogram pass (warp-replicated bins) ----------------
__global__ void hist_k() {
    int blk = blockIdx.x;
    int b = blk >> 6, chunk = blk & 63;
    const float4* sp = (const float4*)&g_sim[(size_t)b * NPG * NPG + (size_t)chunk * 4096];
    float vmin = sigmoidf_(g_smin[b]);
    float vmax = sigmoidf_(g_smax[b]);
    float width = (vmax - vmin) * (1.0f / D_BINS);
    float inv = 1.0f / (width > 0.0f ? width : 1.0f);
    __shared__ int h[8][D_BINS];
    if (threadIdx.x < 8 * D_BINS) h[threadIdx.x >> 4][threadIdx.x & 15] = 0;
    __syncthreads();
    int warp = threadIdx.x >> 5;
    for (int i = threadIdx.x; i < 1024; i += 256) {
        float4 q = sp[i];
        float vv[4] = {q.x, q.y, q.z, q.w};
#pragma unroll
        for (int j = 0; j < 4; j++) {
            float v = sigmoidf_(vv[j]);
            int bi = (int)floorf((v - vmin) * inv);
            bi = bi < 0 ? 0 : (bi > 15 ? 15 : bi);
            atomicAdd(&h[warp][bi], 1);
        }
    }
    __syncthreads();
    if (threadIdx.x < D_BINS) {
        int s = 0;
#pragma unroll
        for (int w = 0; w < 8; w++) s += h[w][threadIdx.x];
        atomicAdd(&g_hist[b * D_BINS + threadIdx.x], s);
    }
}

// ---------------- final head (one block per graph, 128 threads) ----------
__global__ void final_k(const float* __restrict__ Wt, const float* __restrict__ Wtb,
                        const float* __restrict__ tb, const float* __restrict__ W1,
                        const float* __restrict__ b1, const float* __restrict__ Ws,
                        const float* __restrict__ bs, float* __restrict__ out) {
    int b = blockIdx.x, t = threadIdx.x;
    __shared__ float p1s[64], p2s[64];
    __shared__ float scp[64 * 16];
    __shared__ float feat[32];
    __shared__ float hs[32];
    if (t < 64) {
        p1s[t] = g_pool[0][b * 64 + t];
        p2s[t] = g_pool[1][b * 64 + t];
    }
    __syncthreads();
    if (t < 64) {
        float s[16];
#pragma unroll
        for (int k = 0; k < 16; k++) s[k] = 0.0f;
        for (int j = 0; j < 64; j++) {
            float pj = p2s[j];
            const float* wp = &Wt[(size_t)(t * 64 + j) * 16];
#pragma unroll
            for (int k = 0; k < 16; k++) s[k] += wp[k] * pj;
        }
        float p1v = p1s[t];
#pragma unroll
        for (int k = 0; k < 16; k++) scp[t * 16 + k] = p1v * s[k];
    }
    __syncthreads();
    if (t < 16) {
        float acc = tb[t];
        for (int i = 0; i < 64; i++) acc += scp[i * 16 + t];
        float blk = 0.0f;
        for (int i = 0; i < 64; i++) blk += Wtb[t * 128 + i] * p1s[i];
        for (int i = 0; i < 64; i++) blk += Wtb[t * 128 + 64 + i] * p2s[i];
        float tv = acc + blk;
        feat[t] = fmaxf(tv, 0.0f);
        feat[16 + t] = (float)g_hist[b * 16 + t] * (1.0f / ((float)NPG * (float)NPG));
    }
    __syncthreads();
    if (t < 32) {
        float acc = b1[t];
        for (int i = 0; i < 32; i++) acc += feat[i] * W1[i * 32 + t];
        hs[t] = fmaxf(acc, 0.0f);
    }
    __syncthreads();
    if (t == 0) {
        float acc = bs[0];
        for (int j = 0; j < 32; j++) acc += hs[j] * Ws[j];
        out[b] = sigmoidf_(acc);
    }
}

// ---------------- launcher ----------------
extern "C" void kernel_launch(void* const* d_in, const int* in_sizes, int n_in,
                              void* d_out, int out_size) {
    const float* x1  = (const float*)d_in[0];
    const float* x2  = (const float*)d_in[1];
    const int* ei1   = (const int*)d_in[2];
    const int* ei2   = (const int*)d_in[3];
    const float* Wc1 = (const float*)d_in[6];
    const float* bc1 = (const float*)d_in[7];
    const float* Wc2 = (const float*)d_in[8];
    const float* bc2 = (const float*)d_in[9];
    const float* Wc3 = (const float*)d_in[10];
    const float* bc3 = (const float*)d_in[11];
    const float* Watt = (const float*)d_in[12];
    const float* Wt  = (const float*)d_in[13];
    const float* Wtb = (const float*)d_in[14];
    const float* tb  = (const float*)d_in[15];
    const float* W1  = (const float*)d_in[16];
    const float* b1  = (const float*)d_in[17];
    const float* Ws  = (const float*)d_in[18];
    const float* bs  = (const float*)d_in[19];
    float* out = (float*)d_out;

    void* p;
    float *buf0, *buf1, *feat;
    cudaGetSymbolAddress(&p, g_buf0); buf0 = (float*)p;
    cudaGetSymbolAddress(&p, g_buf1); buf1 = (float*)p;
    cudaGetSymbolAddress(&p, g_feat); feat = (float*)p;

    // opt-in to large dynamic smem for the staged agg kernels (idempotent)
    cudaFuncSetAttribute(agg_smem_k<32, false, false>,
                         cudaFuncAttributeMaxDynamicSharedMemorySize, NPG * 32 * 4);
    cudaFuncSetAttribute(agg_smem_k<96, true, true>,
                         cudaFuncAttributeMaxDynamicSharedMemorySize, NPG * 96 * 4);
    cudaFuncSetAttribute(agg_smem_k<64, true, false>,
                         cudaFuncAttributeMaxDynamicSharedMemorySize, NPG * 64 * 4);

    init_k<<<NTOT / 256, 256>>>();

    // CSR build for BOTH sides (batched over grid.y)
    deg_k<<<dim3(NEDGE / 256, 2), 256>>>(ei1 + NEDGE, ei2 + NEDGE);
    dinv_k<<<dim3(NTOT / 256, 2), 256>>>();
    scanA_k<<<dim3(256, 2), 256>>>();
    scanB_k<<<2, 256>>>();
    scanC_k<<<dim3(256, 2), 256>>>();
    scatter_k<<<dim3(NEDGE / 256, 2), 256>>>(ei1, ei2);

    for (int side = 0; side < 2; side++) {
        const float* x = side ? x2 : x1;
        float* fout = feat + (size_t)side * NTOT * 64;

        // layer 1: aggregate x (32 feats) first, then GEMM 32->128 (+bias,relu)
        agg_smem_k<32, false, false><<<NB, 512, NPG * 32 * 4>>>(x, nullptr, buf0, side);
        gemm_mma_k<32, 128, true, true><<<NTOT / 128, 256>>>(buf0, Wc1, bc1, buf1);

        // layer 2: GEMM 128->96 (no bias), then aggregate 96 (+bias,relu)
        gemm_mma_k<128, 96, false, false><<<NTOT / 128, 256>>>(buf1, Wc2, nullptr, buf0);
        agg_smem_k<96, true, true><<<NB, 512, NPG * 96 * 4>>>(buf0, bc2, buf1, side);

        // layer 3: GEMM 96->64 (no bias), then aggregate 64 (+bias)
        gemm_mma_k<96, 64, false, false><<<NTOT / 128, 256>>>(buf1, Wc3, nullptr, buf0);
        agg_smem_k<64, true, false><<<NB, 512, NPG * 64 * 4>>>(buf0, bc3, fout, side);

        pool_k<<<NB, 256>>>(side, Watt);
    }

    sim_mma_k<<<dim3(4, 4, NB), 256>>>();
    hist_k<<<NB * 64, 256>>>();
    final_k<<<NB, 128>>>(Wt, Wtb, tb, W1, b1, Ws, bs, out);
}

// round 7
// speedup vs baseline: 1.1145x; 1.1145x over previous
#include <cuda_runtime.h>
#include <math.h>
#include <cfloat>
#include <stdint.h>

// ---------------- problem dims (fixed) ----------------
#define NTOT  65536      // nodes per side (B*N)
#define NEDGE 524288     // edges per side
#define NB    128        // graphs
#define NPG   512        // nodes per graph
#define D_F1  128
#define D_F2  96
#define D_F3  64
#define D_BINS 16

// ---------------- device scratch (per-side slabs for batched launches) -----
__device__ float g_bufA[2][NTOT * D_F1];
__device__ float g_bufB[2][NTOT * D_F1];
__device__ float g_feat[2][NTOT * D_F3];
__device__ float g_dinv[2][NTOT];
__device__ int   g_degi[2][NTOT];
__device__ int   g_row[2][NTOT + 1];
__device__ int   g_cursor[2][NTOT];
__device__ int   g_bsum[2][256];
__device__ int   g_boff[2][256];
__device__ int   g_esrc[2][NEDGE];
__device__ float g_enorm[2][NEDGE];
__device__ float g_sim[(size_t)NB * NPG * NPG];
__device__ int   g_hist[NB * D_BINS];
__device__ float g_smin[NB];
__device__ float g_smax[NB];
__device__ float g_pool[2][NB * D_F3];

__device__ __forceinline__ float sigmoidf_(float x) { return 1.0f / (1.0f + expf(-x)); }

__device__ __forceinline__ void atomicMinFloat(float* addr, float val) {
    int old = __float_as_int(*addr);
    while (__int_as_float(old) > val) {
        int assumed = old;
        old = atomicCAS((int*)addr, assumed, __float_as_int(val));
        if (old == assumed) break;
    }
}
__device__ __forceinline__ void atomicMaxFloat(float* addr, float val) {
    int old = __float_as_int(*addr);
    while (__int_as_float(old) < val) {
        int assumed = old;
        old = atomicCAS((int*)addr, assumed, __float_as_int(val));
        if (old == assumed) break;
    }
}

// ---------------- tf32 helpers (3xTF32 fp32-emulation split) ----------------
__device__ __forceinline__ uint32_t f2tf32(float x) {
    uint32_t r;
    asm("cvt.rna.tf32.f32 %0, %1;" : "=r"(r) : "f"(x));
    return r;
}
__device__ __forceinline__ void split_tf32(float x, uint32_t& hi, uint32_t& lo) {
    hi = f2tf32(x);
    lo = f2tf32(x - __uint_as_float(hi));
}
__device__ __forceinline__ void mma_tf32(float* d, const uint32_t* a, const uint32_t* b) {
    asm volatile(
        "mma.sync.aligned.m16n8k8.row.col.f32.tf32.tf32.f32 "
        "{%0,%1,%2,%3}, {%4,%5,%6,%7}, {%8,%9}, {%0,%1,%2,%3};\n"
        : "+f"(d[0]), "+f"(d[1]), "+f"(d[2]), "+f"(d[3])
        : "r"(a[0]), "r"(a[1]), "r"(a[2]), "r"(a[3]), "r"(b[0]), "r"(b[1]));
}

// block-wide exclusive scan of 256 ints (one value per thread)
__device__ __forceinline__ int block_exscan_256(int v, int* sm8) {
    int lane = threadIdx.x & 31, w = threadIdx.x >> 5;
    int x = v;
#pragma unroll
    for (int o = 1; o < 32; o <<= 1) {
        int y = __shfl_up_sync(0xffffffffu, x, o);
        if (lane >= o) x += y;
    }
    if (lane == 31) sm8[w] = x;
    __syncthreads();
    if (threadIdx.x < 8) {
        int s = sm8[threadIdx.x];
#pragma unroll
        for (int o = 1; o < 8; o <<= 1) {
            int y = __shfl_up_sync(0xffu, s, o);
            if ((int)threadIdx.x >= o) s += y;
        }
        sm8[threadIdx.x] = s;
    }
    __syncthreads();
    int woff = w ? sm8[w - 1] : 0;
    return woff + x - v;
}

// ---------------- init ----------------
__global__ void init_k() {
    int i = blockIdx.x * blockDim.x + threadIdx.x;
    if (i < NTOT) { g_degi[0][i] = 0; g_degi[1][i] = 0; }
    if (i < NB * D_BINS) g_hist[i] = 0;
    if (i < NB) { g_smin[i] = FLT_MAX; g_smax[i] = -FLT_MAX; }
}

// ---------------- degree / dinv (both sides via grid.y) ----------------
__global__ void deg_k(const int* __restrict__ dst0, const int* __restrict__ dst1) {
    int side = blockIdx.y;
    const int* dst = side ? dst1 : dst0;
    int e = blockIdx.x * blockDim.x + threadIdx.x;
    if (e < NEDGE) atomicAdd(&g_degi[side][dst[e]], 1);
}
__global__ void dinv_k() {
    int side = blockIdx.y;
    int i = blockIdx.x * blockDim.x + threadIdx.x;
    if (i < NTOT) g_dinv[side][i] = rsqrtf((float)g_degi[side][i] + 1.0f);
}

// ---------------- 3-phase parallel scan ----------------
__global__ void scanA_k() {
    int side = blockIdx.y;
    int i = blockIdx.x * 256 + threadIdx.x;
    int v = g_degi[side][i];
#pragma unroll
    for (int o = 16; o; o >>= 1) v += __shfl_xor_sync(0xffffffffu, v, o);
    __shared__ int sm[8];
    if ((threadIdx.x & 31) == 0) sm[threadIdx.x >> 5] = v;
    __syncthreads();
    if (threadIdx.x == 0) {
        int s = 0;
#pragma unroll
        for (int j = 0; j < 8; j++) s += sm[j];
        g_bsum[side][blockIdx.x] = s;
    }
}
__global__ void scanB_k() {
    int side = blockIdx.x;
    __shared__ int sm[8];
    int v = g_bsum[side][threadIdx.x];
    int ex = block_exscan_256(v, sm);
    g_boff[side][threadIdx.x] = ex + v;
}
__global__ void scanC_k() {
    int side = blockIdx.y;
    int i = blockIdx.x * 256 + threadIdx.x;
    int d = g_degi[side][i];
    __shared__ int sm[8];
    int ex = block_exscan_256(d, sm);
    int off = (blockIdx.x ? g_boff[side][blockIdx.x - 1] : 0) + ex;
    g_row[side][i] = off;
    g_cursor[side][i] = off;
    if (i == NTOT - 1) g_row[side][NTOT] = NEDGE;
}

// ---------------- scatter edges into CSR order ----------------
__global__ void scatter_k(const int* __restrict__ ei0, const int* __restrict__ ei1) {
    int side = blockIdx.y;
    const int* ei = side ? ei1 : ei0;
    const int* src = ei;
    const int* dst = ei + NEDGE;
    int e = blockIdx.x * blockDim.x + threadIdx.x;
    if (e >= NEDGE) return;
    int s = src[e], d = dst[e];
    int pos = atomicAdd(&g_cursor[side][d], 1);
    g_esrc[side][pos] = s;
    g_enorm[side][pos] = g_dinv[side][s] * g_dinv[side][d];
}

// ---------------- gather-based aggregation (both sides via grid.y) --------
template <int OUT, bool BIAS, bool RELU>
__global__ void agg_k(const float* __restrict__ xw0, const float* __restrict__ xw1,
                      const float* __restrict__ bias,
                      float* __restrict__ out0, float* __restrict__ out1) {
    constexpr int C4 = OUT / 4;
    int side = blockIdx.y;
    const float* xw = side ? xw1 : xw0;
    float* out = side ? out1 : out0;
    int gid = blockIdx.x * blockDim.x + threadIdx.x;
    int node = gid / C4, chunk = gid % C4;
    if (node >= NTOT) return;
    const float4* xw4 = (const float4*)xw;
    float dv = g_dinv[side][node];
    float dv2 = dv * dv;
    float4 v = xw4[(size_t)node * C4 + chunk];
    float4 acc = make_float4(v.x * dv2, v.y * dv2, v.z * dv2, v.w * dv2);
    int beg = g_row[side][node], end = g_row[side][node + 1];
    for (int e = beg; e < end; e++) {
        int s = g_esrc[side][e];
        float nm = g_enorm[side][e];
        float4 u = xw4[(size_t)s * C4 + chunk];
        acc.x += u.x * nm; acc.y += u.y * nm; acc.z += u.z * nm; acc.w += u.w * nm;
    }
    if (BIAS) {
        acc.x += bias[chunk * 4 + 0];
        acc.y += bias[chunk * 4 + 1];
        acc.z += bias[chunk * 4 + 2];
        acc.w += bias[chunk * 4 + 3];
    }
    if (RELU) {
        acc.x = fmaxf(acc.x, 0.f); acc.y = fmaxf(acc.y, 0.f);
        acc.z = fmaxf(acc.z, 0.f); acc.w = fmaxf(acc.w, 0.f);
    }
    ((float4*)out)[(size_t)node * C4 + chunk] = acc;
}

// ---------------- 3xTF32 tensor-core GEMM (both sides via grid.y) ----------
template <int KIN, int NOUT, bool BIAS, bool RELU>
__global__ void gemm_mma_k(const float* __restrict__ x0, const float* __restrict__ x1,
                           const float* __restrict__ W, const float* __restrict__ bias,
                           float* __restrict__ out0, float* __restrict__ out1) {
    constexpr int KC = 16;
    constexpr int NT = NOUT / 8;
    constexpr int XS = KC + 4;
    constexpr int WS = NOUT + 8;
    __shared__ uint32_t Xh[128 * XS];
    __shared__ uint32_t Xl[128 * XS];
    __shared__ uint32_t Wh[KC * WS];
    __shared__ uint32_t Wl[KC * WS];
    int side = blockIdx.y;
    const float* x = side ? x1 : x0;
    float* out = side ? out1 : out0;
    int tid = threadIdx.x;
    int warp = tid >> 5, lane = tid & 31;
    size_t m0 = (size_t)blockIdx.x * 128;
    float acc[NT][4];
#pragma unroll
    for (int i = 0; i < NT; i++)
#pragma unroll
        for (int j = 0; j < 4; j++) acc[i][j] = 0.0f;

    for (int k0 = 0; k0 < KIN; k0 += KC) {
        for (int i = tid; i < 128 * (KC / 4); i += 256) {
            int r = i / (KC / 4), q = i % (KC / 4);
            float4 v = *(const float4*)&x[(m0 + r) * KIN + k0 + q * 4];
            uint32_t* ph = &Xh[r * XS + q * 4];
            uint32_t* pl = &Xl[r * XS + q * 4];
            split_tf32(v.x, ph[0], pl[0]); split_tf32(v.y, ph[1], pl[1]);
            split_tf32(v.z, ph[2], pl[2]); split_tf32(v.w, ph[3], pl[3]);
        }
        for (int i = tid; i < KC * NOUT / 4; i += 256) {
            int k = i / (NOUT / 4), q = i % (NOUT / 4);
            float4 v = *(const float4*)&W[(size_t)(k0 + k) * NOUT + q * 4];
            uint32_t* ph = &Wh[k * WS + q * 4];
            uint32_t* pl = &Wl[k * WS + q * 4];
            split_tf32(v.x, ph[0], pl[0]); split_tf32(v.y, ph[1], pl[1]);
            split_tf32(v.z, ph[2], pl[2]); split_tf32(v.w, ph[3], pl[3]);
        }
        __syncthreads();
#pragma unroll
        for (int ks = 0; ks < KC / 8; ks++) {
            uint32_t ah[4], al[4];
            int arow = warp * 16 + (lane >> 2);
            int acol = ks * 8 + (lane & 3);
            ah[0] = Xh[arow * XS + acol];       al[0] = Xl[arow * XS + acol];
            ah[1] = Xh[(arow + 8) * XS + acol]; al[1] = Xl[(arow + 8) * XS + acol];
            ah[2] = Xh[arow * XS + acol + 4];   al[2] = Xl[arow * XS + acol + 4];
            ah[3] = Xh[(arow + 8) * XS + acol + 4]; al[3] = Xl[(arow + 8) * XS + acol + 4];
            int bk = ks * 8 + (lane & 3);
            int bn0 = lane >> 2;
#pragma unroll
            for (int nt = 0; nt < NT; nt++) {
                uint32_t bh[2], bl[2];
                bh[0] = Wh[bk * WS + nt * 8 + bn0];
                bh[1] = Wh[(bk + 4) * WS + nt * 8 + bn0];
                bl[0] = Wl[bk * WS + nt * 8 + bn0];
                bl[1] = Wl[(bk + 4) * WS + nt * 8 + bn0];
                mma_tf32(acc[nt], ah, bh);
                mma_tf32(acc[nt], ah, bl);
                mma_tf32(acc[nt], al, bh);
            }
        }
        __syncthreads();
    }
    size_t row = m0 + warp * 16 + (lane >> 2);
    int col0 = (lane & 3) * 2;
#pragma unroll
    for (int nt = 0; nt < NT; nt++) {
        int c = nt * 8 + col0;
        float b0 = BIAS ? bias[c] : 0.0f, b1 = BIAS ? bias[c + 1] : 0.0f;
        float v0 = acc[nt][0] + b0, v1 = acc[nt][1] + b1;
        float v2 = acc[nt][2] + b0, v3 = acc[nt][3] + b1;
        if (RELU) {
            v0 = fmaxf(v0, 0.f); v1 = fmaxf(v1, 0.f);
            v2 = fmaxf(v2, 0.f); v3 = fmaxf(v3, 0.f);
        }
        *(float2*)&out[row * NOUT + c] = make_float2(v0, v1);
        *(float2*)&out[(row + 8) * NOUT + c] = make_float2(v2, v3);
    }
}

// ---------------- attention pooling (grid = (NB, 2)) ----------------
__global__ void pool_k(const float* __restrict__ Watt) {
    int side = blockIdx.y;
    int b = blockIdx.x;
    const float* fb = &g_feat[side][(size_t)b * NPG * D_F3];
    int t = threadIdx.x;  // 256
    __shared__ float p4[4][64];
    __shared__ float meanc[64];
    __shared__ float ctx[64];
    __shared__ float wsum[8][64];
    int d = t & 63, g = t >> 6;
    float loc = 0.0f;
    for (int r = g; r < NPG; r += 4) loc += fb[r * 64 + d];
    p4[g][d] = loc;
    __syncthreads();
    if (t < 64) meanc[t] = (p4[0][t] + p4[1][t] + p4[2][t] + p4[3][t]) * (1.0f / NPG);
    __syncthreads();
    if (t < 64) {
        float c = 0.0f;
        for (int i = 0; i < 64; i++) c += meanc[i] * Watt[i * 64 + t];
        ctx[t] = tanhf(c);
    }
    __syncthreads();
    int w = t >> 5, l = t & 31;
    float a0 = 0.0f, a1 = 0.0f;
    float c0 = ctx[l], c1 = ctx[l + 32];
    for (int r = w * 64; r < w * 64 + 64; r++) {
        float v0 = fb[r * 64 + l], v1 = fb[r * 64 + 32 + l];
        float dp = v0 * c0 + v1 * c1;
#pragma unroll
        for (int o = 16; o; o >>= 1) dp += __shfl_xor_sync(0xffffffffu, dp, o);
        float coef = sigmoidf_(dp);
        a0 += v0 * coef;
        a1 += v1 * coef;
    }
    wsum[w][l] = a0;
    wsum[w][l + 32] = a1;
    __syncthreads();
    if (t < 64) {
        float s = 0.0f;
        for (int w2 = 0; w2 < 8; w2++) s += wsum[w2][t];
        g_pool[side][b * 64 + t] = s;
    }
}

// ---------------- similarity via 3xTF32 mma, 128x128 tile ----------------
__global__ void sim_mma_k() {
    constexpr int KC = 16;
    constexpr int XS = KC + 4;
    int b = blockIdx.z;
    int i0 = blockIdx.y * 128, j0 = blockIdx.x * 128;
    __shared__ uint32_t Ah_s[128 * XS];
    __shared__ uint32_t Al_s[128 * XS];
    __shared__ uint32_t Bh_s[128 * XS];
    __shared__ uint32_t Bl_s[128 * XS];
    const float* f1 = &g_feat[0][(size_t)(b * NPG + i0) * 64];
    const float* f2 = &g_feat[1][(size_t)(b * NPG + j0) * 64];
    int tid = threadIdx.x;
    int warp = tid >> 5, lane = tid & 31;
    int wm = warp >> 2, wn = warp & 3;
    float acc[4][4][4];
#pragma unroll
    for (int mt = 0; mt < 4; mt++)
#pragma unroll
        for (int nt = 0; nt < 4; nt++)
#pragma unroll
            for (int j = 0; j < 4; j++) acc[mt][nt][j] = 0.0f;

    for (int k0 = 0; k0 < 64; k0 += KC) {
        for (int i = tid; i < 128 * (KC / 4); i += 256) {
            int r = i / (KC / 4), q = i % (KC / 4);
            float4 va = *(const float4*)&f1[r * 64 + k0 + q * 4];
            float4 vb = *(const float4*)&f2[r * 64 + k0 + q * 4];
            uint32_t* pah = &Ah_s[r * XS + q * 4];
            uint32_t* pal = &Al_s[r * XS + q * 4];
            uint32_t* pbh = &Bh_s[r * XS + q * 4];
            uint32_t* pbl = &Bl_s[r * XS + q * 4];
            split_tf32(va.x, pah[0], pal[0]); split_tf32(va.y, pah[1], pal[1]);
            split_tf32(va.z, pah[2], pal[2]); split_tf32(va.w, pah[3], pal[3]);
            split_tf32(vb.x, pbh[0], pbl[0]); split_tf32(vb.y, pbh[1], pbl[1]);
            split_tf32(vb.z, pbh[2], pbl[2]); split_tf32(vb.w, pbh[3], pbl[3]);
        }
        __syncthreads();
#pragma unroll
        for (int ks = 0; ks < KC / 8; ks++) {
            int acol = ks * 8 + (lane & 3);
            uint32_t ah[4][4], al[4][4], bh[4][2], bl[4][2];
#pragma unroll
            for (int mt = 0; mt < 4; mt++) {
                int arow = wm * 64 + mt * 16 + (lane >> 2);
                ah[mt][0] = Ah_s[arow * XS + acol];
                ah[mt][1] = Ah_s[(arow + 8) * XS + acol];
                ah[mt][2] = Ah_s[arow * XS + acol + 4];
                ah[mt][3] = Ah_s[(arow + 8) * XS + acol + 4];
                al[mt][0] = Al_s[arow * XS + acol];
                al[mt][1] = Al_s[(arow + 8) * XS + acol];
                al[mt][2] = Al_s[arow * XS + acol + 4];
                al[mt][3] = Al_s[(arow + 8) * XS + acol + 4];
            }
#pragma unroll
            for (int nt = 0; nt < 4; nt++) {
                int bnode = wn * 32 + nt * 8 + (lane >> 2);
                bh[nt][0] = Bh_s[bnode * XS + acol];
                bh[nt][1] = Bh_s[bnode * XS + acol + 4];
                bl[nt][0] = Bl_s[bnode * XS + acol];
                bl[nt][1] = Bl_s[bnode * XS + acol + 4];
            }
#pragma unroll
            for (int mt = 0; mt < 4; mt++)
#pragma unroll
                for (int nt = 0; nt < 4; nt++) {
                    mma_tf32(acc[mt][nt], ah[mt], bh[nt]);
                    mma_tf32(acc[mt][nt], ah[mt], bl[nt]);
                    mma_tf32(acc[mt][nt], al[mt], bh[nt]);
                }
        }
        __syncthreads();
    }
    float lmin = FLT_MAX, lmax = -FLT_MAX;
    float* sp = &g_sim[(size_t)b * NPG * NPG];
    int col0 = (lane & 3) * 2;
#pragma unroll
    for (int mt = 0; mt < 4; mt++) {
        size_t r0 = (size_t)(i0 + wm * 64 + mt * 16 + (lane >> 2));
#pragma unroll
        for (int nt = 0; nt < 4; nt++) {
            int c = j0 + wn * 32 + nt * 8 + col0;
            float v0 = acc[mt][nt][0], v1 = acc[mt][nt][1];
            float v2 = acc[mt][nt][2], v3 = acc[mt][nt][3];
            lmin = fminf(lmin, fminf(fminf(v0, v1), fminf(v2, v3)));
            lmax = fmaxf(lmax, fmaxf(fmaxf(v0, v1), fmaxf(v2, v3)));
            *(float2*)&sp[r0 * NPG + c] = make_float2(v0, v1);
            *(float2*)&sp[(r0 + 8) * NPG + c] = make_float2(v2, v3);
        }
    }
    __shared__ float rmin[256], rmax[256];
    rmin[tid] = lmin;
    rmax[tid] = lmax;
    __syncthreads();
    for (int s = 128; s > 0; s >>= 1) {
        if (tid < s) {
            rmin[tid] = fminf(rmin[tid], rmin[tid + s]);
            rmax[tid] = fmaxf(rmax[tid], rmax[tid + s]);
        }
        __syncthreads();
    }
    if (tid == 0) {
        atomicMinFloat(&g_smin[b], rmin[0]);
        atomicMaxFloat(&g_smax[b], rmax[0]);
    }
}

// ---------------- histogram pass (warp-replicated bins) ----------------
__global__ void hist_k() {
    int blk = blockIdx.x;
    int b = blk >> 6, chunk = blk & 63;
    const float4* sp = (const float4*)&g_sim[(size_t)b * NPG * NPG + (size_t)chunk * 4096];
    float vmin = sigmoidf_(g_smin[b]);
    float vmax = sigmoidf_(g_smax[b]);
    float width = (vmax - vmin) * (1.0f / D_BINS);
    float inv = 1.0f / (width > 0.0f ? width : 1.0f);
    __shared__ int h[8][D_BINS];
    if (threadIdx.x < 8 * D_BINS) h[threadIdx.x >> 4][threadIdx.x & 15] = 0;
    __syncthreads();
    int warp = threadIdx.x >> 5;
    for (int i = threadIdx.x; i < 1024; i += 256) {
        float4 q = sp[i];
        float vv[4] = {q.x, q.y, q.z, q.w};
#pragma unroll
        for (int j = 0; j < 4; j++) {
            float v = sigmoidf_(vv[j]);
            int bi = (int)floorf((v - vmin) * inv);
            bi = bi < 0 ? 0 : (bi > 15 ? 15 : bi);
            atomicAdd(&h[warp][bi], 1);
        }
    }
    __syncthreads();
    if (threadIdx.x < D_BINS) {
        int s = 0;
#pragma unroll
        for (int w = 0; w < 8; w++) s += h[w][threadIdx.x];
        atomicAdd(&g_hist[b * D_BINS + threadIdx.x], s);
    }
}

// ---------------- final head (one block per graph, 128 threads) ----------
__global__ void final_k(const float* __restrict__ Wt, const float* __restrict__ Wtb,
                        const float* __restrict__ tb, const float* __restrict__ W1,
                        const float* __restrict__ b1, const float* __restrict__ Ws,
                        const float* __restrict__ bs, float* __restrict__ out) {
    int b = blockIdx.x, t = threadIdx.x;
    __shared__ float p1s[64], p2s[64];
    __shared__ float scp[64 * 16];
    __shared__ float feat[32];
    __shared__ float hs[32];
    if (t < 64) {
        p1s[t] = g_pool[0][b * 64 + t];
        p2s[t] = g_pool[1][b * 64 + t];
    }
    __syncthreads();
    if (t < 64) {
        float s[16];
#pragma unroll
        for (int k = 0; k < 16; k++) s[k] = 0.0f;
        for (int j = 0; j < 64; j++) {
            float pj = p2s[j];
            const float* wp = &Wt[(size_t)(t * 64 + j) * 16];
#pragma unroll
            for (int k = 0; k < 16; k++) s[k] += wp[k] * pj;
        }
        float p1v = p1s[t];
#pragma unroll
        for (int k = 0; k < 16; k++) scp[t * 16 + k] = p1v * s[k];
    }
    __syncthreads();
    if (t < 16) {
        float acc = tb[t];
        for (int i = 0; i < 64; i++) acc += scp[i * 16 + t];
        float blk = 0.0f;
        for (int i = 0; i < 64; i++) blk += Wtb[t * 128 + i] * p1s[i];
        for (int i = 0; i < 64; i++) blk += Wtb[t * 128 + 64 + i] * p2s[i];
        float tv = acc + blk;
        feat[t] = fmaxf(tv, 0.0f);
        feat[16 + t] = (float)g_hist[b * 16 + t] * (1.0f / ((float)NPG * (float)NPG));
    }
    __syncthreads();
    if (t < 32) {
        float acc = b1[t];
        for (int i = 0; i < 32; i++) acc += feat[i] * W1[i * 32 + t];
        hs[t] = fmaxf(acc, 0.0f);
    }
    __syncthreads();
    if (t == 0) {
        float acc = bs[0];
        for (int j = 0; j < 32; j++) acc += hs[j] * Ws[j];
        out[b] = sigmoidf_(acc);
    }
}

// ---------------- launcher ----------------
extern "C" void kernel_launch(void* const* d_in, const int* in_sizes, int n_in,
                              void* d_out, int out_size) {
    const float* x1  = (const float*)d_in[0];
    const float* x2  = (const float*)d_in[1];
    const int* ei1   = (const int*)d_in[2];
    const int* ei2   = (const int*)d_in[3];
    const float* Wc1 = (const float*)d_in[6];
    const float* bc1 = (const float*)d_in[7];
    const float* Wc2 = (const float*)d_in[8];
    const float* bc2 = (const float*)d_in[9];
    const float* Wc3 = (const float*)d_in[10];
    const float* bc3 = (const float*)d_in[11];
    const float* Watt = (const float*)d_in[12];
    const float* Wt  = (const float*)d_in[13];
    const float* Wtb = (const float*)d_in[14];
    const float* tb  = (const float*)d_in[15];
    const float* W1  = (const float*)d_in[16];
    const float* b1  = (const float*)d_in[17];
    const float* Ws  = (const float*)d_in[18];
    const float* bs  = (const float*)d_in[19];
    float* out = (float*)d_out;

    void* p;
    float *a0, *a1, *b0, *b1p, *f0, *f1;
    cudaGetSymbolAddress(&p, g_bufA);
    a0 = (float*)p; a1 = a0 + (size_t)NTOT * D_F1;
    cudaGetSymbolAddress(&p, g_bufB);
    b0 = (float*)p; b1p = b0 + (size_t)NTOT * D_F1;
    cudaGetSymbolAddress(&p, g_feat);
    f0 = (float*)p; f1 = f0 + (size_t)NTOT * D_F3;

    init_k<<<NTOT / 256, 256>>>();

    // CSR build for BOTH sides (batched over grid.y)
    deg_k<<<dim3(NEDGE / 256, 2), 256>>>(ei1 + NEDGE, ei2 + NEDGE);
    dinv_k<<<dim3(NTOT / 256, 2), 256>>>();
    scanA_k<<<dim3(256, 2), 256>>>();
    scanB_k<<<2, 256>>>();
    scanC_k<<<dim3(256, 2), 256>>>();
    scatter_k<<<dim3(NEDGE / 256, 2), 256>>>(ei1, ei2);

    // conv pipeline, both sides per launch
    // layer 1: aggregate x (32 feats), then GEMM 32->128 (+bias,relu)
    agg_k<32, false, false><<<dim3(NTOT * 8 / 256, 2), 256>>>(x1, x2, nullptr, a0, a1);
    gemm_mma_k<32, 128, true, true><<<dim3(NTOT / 128, 2), 256>>>(a0, a1, Wc1, bc1, b0, b1p);

    // layer 2: GEMM 128->96, then aggregate 96 (+bias,relu)
    gemm_mma_k<128, 96, false, false><<<dim3(NTOT / 128, 2), 256>>>(b0, b1p, Wc2, nullptr, a0, a1);
    agg_k<96, true, true><<<dim3(NTOT * 24 / 256, 2), 256>>>(a0, a1, bc2, b0, b1p);

    // layer 3: GEMM 96->64, then aggregate 64 (+bias)
    gemm_mma_k<96, 64, false, false><<<dim3(NTOT / 128, 2), 256>>>(b0, b1p, Wc3, nullptr, a0, a1);
    agg_k<64, true, false><<<dim3(NTOT * 16 / 256, 2), 256>>>(a0, a1, bc3, f0, f1);

    pool_k<<<dim3(NB, 2), 256>>>(Watt);

    sim_mma_k<<<dim3(4, 4, NB), 256>>>();
    hist_k<<<NB * 64, 256>>>();
    final_k<<<NB, 128>>>(Wt, Wtb, tb, W1, b1, Ws, bs, out);
}